// round 13
// baseline (speedup 1.0000x reference)
#include <cuda_runtime.h>

#define TB 64      // 2 warps per CTA, unit-split over the same 128 elements
#define EPT 4      // batch elements per thread (per lane)
#define ELPB 128   // elements per CTA (32 lanes * EPT)
#define MAXB 131072

typedef unsigned long long u64;

// scratch: z transposed [48][B], en staged [48][B]
__device__ float g_zt[(size_t)48 * MAXB];
__device__ float g_en[(size_t)48 * MAXB];

__device__ __forceinline__ u64 pk(float lo, float hi) {
    u64 r; asm("mov.b64 %0,{%1,%2};" : "=l"(r) : "f"(lo), "f"(hi)); return r;
}
__device__ __forceinline__ void upk(u64 v, float& lo, float& hi) {
    asm("mov.b64 {%0,%1},%2;" : "=f"(lo), "=f"(hi) : "l"(v));
}
__device__ __forceinline__ u64 ffma2(u64 a, u64 b, u64 c) {
    u64 d; asm("fma.rn.f32x2 %0,%1,%2,%3;" : "=l"(d) : "l"(a), "l"(b), "l"(c)); return d;
}
__device__ __forceinline__ float tanha(float x) {
    float y; asm("tanh.approx.f32 %0,%1;" : "=f"(y) : "f"(x)); return y;
}
// i/f/o gate rows pre-scaled by 0.5: sigmoid(x) = fmaf(tanh(x/2),0.5,0.5)
__device__ __forceinline__ float sigp(float a_half) {
    return fmaf(tanha(a_half), 0.5f, 0.5f);
}

#define COMP(v, e) ((e) == 0 ? (v).x : (e) == 1 ? (v).y : (e) == 2 ? (v).z : (v).w)

struct __align__(16) SW {
    u64 Wim[128];   // main LSTM input pairs  [64 rows][2] (real pairs, scaled)
    u64 Whm[512];   // main LSTM hidden pairs [64 rows][8]
    u64 Wie[128];   // encoder input pairs
    u64 Whe[512];   // encoder hidden pairs
    u64 Bm[64];     // (scaled bias, 0)
    u64 Be[64];
    float Wlf[12 * 16];
    float Blf[12];
    float W1[128];
    float W2[32];
    float Wenc[64];
    float B1[8];
    float B2m[4];
    float Benc[4];
    float gg[8];    // Wg[0..2], bg, Wg2[0..2], bg2
};

// Half-cell: this warp computes units [warp*8, warp*8+8) for 4 elements,
// reading the FULL h (hp, in registers) and writing its h pairs into hbuf.
// Caller barriers and reloads hp afterwards. c in SMEM (cs, per-warp units).
__device__ __forceinline__ void cellw(
    const u64* __restrict__ wi,    // [64][2] pairs
    const u64* __restrict__ wh,    // [64][8] pairs
    const u64* __restrict__ bias,  // [64] (b,0)
    const u64 (&xe)[4][2], const u64 (&hp)[4][8],
    float4* __restrict__ cs,       // + tid; index [ul*TB]
    u64* __restrict__ hbuf,        // write buffer (this step's parity)
    int warp, int lane)
{
    const ulonglong2* wi2 = (const ulonglong2*)wi;
    const ulonglong2* wh2 = (const ulonglong2*)wh;
    float hv_ev[4];
#pragma unroll 4
    for (int ul = 0; ul < 8; ul++) {
        const int u = warp * 8 + ul;
        float4 cc = cs[ul * TB];
        u64 A[4][4];
#pragma unroll
        for (int g = 0; g < 4; g++) {
            ulonglong2 w = wi2[u + 16 * g];
            u64 b = bias[u + 16 * g];
#pragma unroll
            for (int e = 0; e < 4; e++) {
                A[g][e] = ffma2(xe[e][0], w.x, b);
                A[g][e] = ffma2(xe[e][1], w.y, A[g][e]);
            }
        }
#pragma unroll
        for (int m = 0; m < 4; m++) {
#pragma unroll
            for (int g = 0; g < 4; g++) {
                ulonglong2 w = wh2[(u + 16 * g) * 4 + m];
#pragma unroll
                for (int e = 0; e < 4; e++) {
                    A[g][e] = ffma2(hp[e][2 * m], w.x, A[g][e]);
                    A[g][e] = ffma2(hp[e][2 * m + 1], w.y, A[g][e]);
                }
            }
        }
        float cn4[4];
#pragma unroll
        for (int e = 0; e < 4; e++) {
            float il, ih, fl, fh, gl, gh, ol, oh;
            upk(A[0][e], il, ih); upk(A[1][e], fl, fh);
            upk(A[2][e], gl, gh); upk(A[3][e], ol, oh);
            float iv = il + ih, fv = fl + fh, gv = gl + gh, ov = ol + oh;
            float ci = sigp(iv);
            float cf = sigp(fv);
            float os = sigp(ov);
            float gt = tanha(gv);
            float cn = cf * COMP(cc, e) + ci * gt;
            cn4[e] = cn;
            float hv = os * tanha(cn);
            if ((ul & 1) == 0) {
                hv_ev[e] = hv;
            } else {
                int pm = warp * 4 + (ul >> 1);   // global h-pair index
                hbuf[(e * 8 + pm) * 32 + lane] = pk(hv_ev[e], hv);
            }
        }
        cs[ul * TB] = make_float4(cn4[0], cn4[1], cn4[2], cn4[3]);
    }
}

// Transpose z [B][48] -> g_zt [48][B] for coalesced recurrent loads.
__global__ void zt_kernel(const float* __restrict__ z, int B)
{
    __shared__ float ts[64 * 49];
    const int e0 = blockIdx.x * 64;
    const int cnt = min(64, B - e0);
    const float4* zp = (const float4*)(z + (size_t)e0 * 48);
    for (int i = threadIdx.x; i < 768; i += 256) {
        int base = i * 4;
        int el = base / 48, v = base % 48;
        if (el < cnt) {
            float4 w = zp[i];
            ts[el * 49 + v] = w.x; ts[el * 49 + v + 1] = w.y;
            ts[el * 49 + v + 2] = w.z; ts[el * 49 + v + 3] = w.w;
        }
    }
    __syncthreads();
    for (int i = threadIdx.x; i < 3072; i += 256) {
        int v = i >> 6, el = i & 63;
        if (el < cnt)
            g_zt[(size_t)v * B + e0 + el] = ts[el * 49 + v];
    }
}

__global__ void __launch_bounds__(TB, 5) stae_main(
    const float* __restrict__ x,
    const float* __restrict__ W_ih, const float* __restrict__ W_hh,
    const float* __restrict__ b_ih, const float* __restrict__ b_hh,
    const float* __restrict__ mW1, const float* __restrict__ mb1,
    const float* __restrict__ mW2, const float* __restrict__ mb2,
    const float* __restrict__ Wg, const float* __restrict__ bg,
    const float* __restrict__ Wg2, const float* __restrict__ bg2,
    const float* __restrict__ Wl, const float* __restrict__ bl,
    const float* __restrict__ We_ih, const float* __restrict__ We_hh,
    const float* __restrict__ be_ih, const float* __restrict__ be_hh,
    const float* __restrict__ Wenc, const float* __restrict__ benc,
    float* __restrict__ out, int B)
{
    __shared__ SW s;
    __shared__ float4 c_sh[8 * TB];    // 8KB: c for [local unit][tid]
    __shared__ u64 h_sh[2 * 1024];     // 16KB: double-buffered h pairs
    const int tid = threadIdx.x;
    const int lane = tid & 31;
    const int warp = tid >> 5;

    // ---- weight fill: real pairs, i/f/o rows pre-scaled by 0.5 --------------
    for (int i = tid; i < 128; i += TB) {
        int r = i >> 1, j = i & 1;
        float sc = ((r >> 4) == 2) ? 1.f : 0.5f;
        s.Wim[i] = pk(W_ih[r * 4 + 2 * j] * sc, W_ih[r * 4 + 2 * j + 1] * sc);
        s.Wie[i] = pk(We_ih[r * 4 + 2 * j] * sc, We_ih[r * 4 + 2 * j + 1] * sc);
    }
    for (int i = tid; i < 512; i += TB) {
        int r = i >> 3, m = i & 7;
        float sc = ((r >> 4) == 2) ? 1.f : 0.5f;
        s.Whm[i] = pk(W_hh[r * 16 + 2 * m] * sc, W_hh[r * 16 + 2 * m + 1] * sc);
        s.Whe[i] = pk(We_hh[r * 16 + 2 * m] * sc, We_hh[r * 16 + 2 * m + 1] * sc);
    }
    for (int i = tid; i < 64; i += TB) {
        float sc = ((i >> 4) == 2) ? 1.f : 0.5f;
        s.Bm[i] = pk((b_ih[i] + b_hh[i]) * sc, 0.f);
        s.Be[i] = pk((be_ih[i] + be_hh[i]) * sc, 0.f);
        s.Wenc[i] = Wenc[i];
    }
    for (int i = tid; i < 156; i += TB) s.Wlf[(i / 13) * 16 + (i % 13)] = Wl[i];
    for (int i = tid; i < 128; i += TB) s.W1[i] = mW1[i];
    if (tid < 32) s.W2[tid] = mW2[tid];
    if (tid < 12) s.Blf[tid] = bl[tid];
    if (tid < 8)  s.B1[tid] = mb1[tid];
    if (tid < 4)  { s.B2m[tid] = mb2[tid]; s.Benc[tid] = benc[tid]; }
    if (tid < 3)  { s.gg[tid] = Wg[tid]; s.gg[4 + tid] = Wg2[tid]; }
    if (tid == 3) { s.gg[3] = bg[0]; s.gg[7] = bg2[0]; }
    __syncthreads();

    const int ctaBase = blockIdx.x * ELPB;
    const int e0 = ctaBase + lane * EPT;           // same elements for both warps
    const int e0c = (e0 + EPT <= B) ? e0 : (B > EPT ? B - EPT : 0);

    float4* cs = c_sh + tid;
    u64* hb0 = h_sh;
    u64* hb1 = h_sh + 1024;
    u64 hp[4][8];
    u64 xe[4][2];
#pragma unroll
    for (int e = 0; e < 4; e++)
#pragma unroll
        for (int m = 0; m < 8; m++) hp[e][m] = 0ull;
#pragma unroll
    for (int k = 0; k < 8; k++) cs[k * TB] = make_float4(0.f, 0.f, 0.f, 0.f);

    // ---------------- phase 1: main LSTM over z_t (coalesced) ----------------
    {
        float4 zv[4], zn[4];
#pragma unroll
        for (int q = 0; q < 4; q++) zv[q] = *(const float4*)(g_zt + (size_t)q * B + e0c);
#pragma unroll 1
        for (int t = 0; t < 12; t++) {
            if (t < 11) {
#pragma unroll
                for (int q = 0; q < 4; q++)
                    zn[q] = *(const float4*)(g_zt + (size_t)((t + 1) * 4 + q) * B + e0c);
            }
#pragma unroll
            for (int e = 0; e < 4; e++) {
                xe[e][0] = pk(COMP(zv[0], e), COMP(zv[1], e));
                xe[e][1] = pk(COMP(zv[2], e), COMP(zv[3], e));
            }
            u64* hb = (t & 1) ? hb1 : hb0;
            cellw(s.Wim, s.Whm, s.Bm, xe, hp, cs, hb, warp, lane);
            __syncthreads();
#pragma unroll
            for (int e = 0; e < 4; e++)
#pragma unroll
                for (int m = 0; m < 8; m++) hp[e][m] = hb[(e * 8 + m) * 32 + lane];
#pragma unroll
            for (int q = 0; q < 4; q++) zv[q] = zn[q];
        }
    }

    // ------------- epilogue: mlp -> gcn2 -> v_out -> en (j split by warp) ----
#pragma unroll 1
    for (int jj = 0; jj < 2; jj++) {
        const int j = warp * 2 + jj;
        float hs[16];
#pragma unroll
        for (int k = 0; k < 16; k++) {
            float a, b; upk(hp[j][k >> 1], a, b); hs[k] = (k & 1) ? b : a;
        }
        float m1[8];
#pragma unroll
        for (int w1 = 0; w1 < 8; w1++) {
            float a = s.B1[w1];
#pragma unroll
            for (int k = 0; k < 16; k++) a += hs[k] * s.W1[w1 * 16 + k];
            m1[w1] = fmaxf(a, 0.f);
        }
        float mo[4];
#pragma unroll
        for (int n = 0; n < 4; n++) {
            float a = s.B2m[n];
#pragma unroll
            for (int w2 = 0; w2 < 8; w2++) a += m1[w2] * s.W2[n * 8 + w2];
            mo[n] = a;
        }
        float q0 = s.gg[4], q1 = s.gg[5], q2 = s.gg[6], qb = s.gg[7];
        float x1_0 = mo[1], x1_1 = mo[0] + mo[2], x1_2 = mo[1] + mo[3], x1_3 = mo[2];
        float x2_0 = x1_1, x2_1 = x1_0 + x1_2, x2_2 = x1_1 + x1_3, x2_3 = x1_2;
        float mg[4];
        mg[0] = q0 * mo[0] + q1 * x1_0 + q2 * x2_0 + qb;
        mg[1] = q0 * mo[1] + q1 * x1_1 + q2 * x2_1 + qb;
        mg[2] = q0 * mo[2] + q1 * x1_2 + q2 * x2_2 + qb;
        mg[3] = q0 * mo[3] + q1 * x1_3 + q2 * x2_3 + qb;

        const int e = e0c + j;
        float xr[48];
        {
            const float4* xb = (const float4*)(x + (size_t)e * 48);
#pragma unroll
            for (int q = 0; q < 12; q++) {
                float4 v = xb[q];
                xr[q * 4 + 0] = v.x; xr[q * 4 + 1] = v.y;
                xr[q * 4 + 2] = v.z; xr[q * 4 + 3] = v.w;
            }
        }
        const float g0_ = s.gg[0], g1_ = s.gg[1], g2_ = s.gg[2], gb_ = s.gg[3];
        const bool wr = (e0 + j) < B;
#pragma unroll 1
        for (int t = 0; t < 12; t++) {
            float vc[4];
#pragma unroll
            for (int n = 0; n < 4; n++) {
                float a = s.Blf[t] + mg[n] * s.Wlf[t * 16 + 12];
#pragma unroll
                for (int k = 0; k < 12; k++) a += xr[n * 12 + k] * s.Wlf[t * 16 + k];
                vc[n] = a;
            }
            float xc0 = xr[t], xc1 = xr[12 + t], xc2 = xr[24 + t], xc3 = xr[36 + t];
            float a1_0 = xc1, a1_1 = xc0 + xc2, a1_2 = xc1 + xc3, a1_3 = xc2;
            float a2_0 = a1_1, a2_1 = a1_0 + a1_2, a2_2 = a1_1 + a1_3, a2_3 = a1_2;
            float d1_0 = vc[1], d1_1 = vc[0] + vc[2], d1_2 = vc[1] + vc[3], d1_3 = vc[2];
            float d2_0 = d1_1, d2_1 = d1_0 + d1_2, d2_2 = d1_1 + d1_3, d2_3 = d1_2;
            float en0 = g0_ * xc0 + g1_ * a1_0 + g2_ * a2_0 + gb_ + q0 * vc[0] + q1 * d1_0 + q2 * d2_0 + qb;
            float en1 = g0_ * xc1 + g1_ * a1_1 + g2_ * a2_1 + gb_ + q0 * vc[1] + q1 * d1_1 + q2 * d2_1 + qb;
            float en2 = g0_ * xc2 + g1_ * a1_2 + g2_ * a2_2 + gb_ + q0 * vc[2] + q1 * d1_2 + q2 * d2_2 + qb;
            float en3 = g0_ * xc3 + g1_ * a1_3 + g2_ * a2_3 + gb_ + q0 * vc[3] + q1 * d1_3 + q2 * d2_3 + qb;
            if (wr) {
                g_en[(size_t)(0 * 12 + t) * B + e] = en0;
                g_en[(size_t)(1 * 12 + t) * B + e] = en1;
                g_en[(size_t)(2 * 12 + t) * B + e] = en2;
                g_en[(size_t)(3 * 12 + t) * B + e] = en3;
            }
        }
    }

    // ---------------- phase 3: encoder LSTM over en (coalesced) ---------------
#pragma unroll
    for (int e = 0; e < 4; e++)
#pragma unroll
        for (int m = 0; m < 8; m++) hp[e][m] = 0ull;
#pragma unroll
    for (int k = 0; k < 8; k++) cs[k * TB] = make_float4(0.f, 0.f, 0.f, 0.f);
    __syncthreads();   // epilogue writes to g_en done CTA-wide before reads
    {
        float4 ev[4], en2[4];
#pragma unroll
        for (int n = 0; n < 4; n++) ev[n] = *(const float4*)(g_en + (size_t)(n * 12) * B + e0c);
#pragma unroll 1
        for (int t = 0; t < 12; t++) {
            if (t < 11) {
#pragma unroll
                for (int n = 0; n < 4; n++)
                    en2[n] = *(const float4*)(g_en + (size_t)(n * 12 + t + 1) * B + e0c);
            }
#pragma unroll
            for (int e = 0; e < 4; e++) {
                xe[e][0] = pk(COMP(ev[0], e), COMP(ev[1], e));
                xe[e][1] = pk(COMP(ev[2], e), COMP(ev[3], e));
            }
            u64* hb = (t & 1) ? hb1 : hb0;
            cellw(s.Wie, s.Whe, s.Be, xe, hp, cs, hb, warp, lane);
            __syncthreads();
#pragma unroll
            for (int e = 0; e < 4; e++)
#pragma unroll
                for (int m = 0; m < 8; m++) hp[e][m] = hb[(e * 8 + m) * 32 + lane];
#pragma unroll
            for (int n = 0; n < 4; n++) ev[n] = en2[n];
        }
    }

    // ---------------- final projection -> lut (overlaid on hb0) --------------
    // Final cell wrote hb1 (t=11); reloads done; hb0 region is free.
    float* lutF = (float*)hb0;   // 128 elems * 4 floats = 2KB
#pragma unroll 1
    for (int jj = 0; jj < 2; jj++) {
        const int j = warp * 2 + jj;
        float hs[16];
#pragma unroll
        for (int k = 0; k < 16; k++) {
            float a, b; upk(hp[j][k >> 1], a, b); hs[k] = (k & 1) ? b : a;
        }
#pragma unroll
        for (int n = 0; n < 4; n++) {
            float a = s.Benc[n];
#pragma unroll
            for (int k = 0; k < 16; k++) a += hs[k] * s.Wenc[n * 16 + k];
            lutF[(lane * 4 + j) * 4 + n] = a;
        }
    }
    __syncthreads();

    // CTA block = 128 rows x 48 floats = 1536 float4s, coalesced
    float4* ob = (float4*)(out + (size_t)ctaBase * 48);
#pragma unroll 1
    for (int r = 0; r < 24; r++) {
        int f = r * TB + tid;
        int el = f / 12;
        int jj2 = f % 12;
        if (ctaBase + el < B) {
            float v = lutF[el * 4 + jj2 / 3];
            ob[f] = make_float4(v, v, v, v);
        }
    }
}

extern "C" void kernel_launch(void* const* d_in, const int* in_sizes, int n_in,
                              void* d_out, int out_size)
{
    const float* x     = (const float*)d_in[0];
    const float* z     = (const float*)d_in[1];
    const float* W_ih  = (const float*)d_in[2];
    const float* W_hh  = (const float*)d_in[3];
    const float* b_ih  = (const float*)d_in[4];
    const float* b_hh  = (const float*)d_in[5];
    const float* mW1   = (const float*)d_in[6];
    const float* mb1   = (const float*)d_in[7];
    const float* mW2   = (const float*)d_in[8];
    const float* mb2   = (const float*)d_in[9];
    const float* Wg    = (const float*)d_in[10];
    const float* bg    = (const float*)d_in[11];
    const float* Wg2   = (const float*)d_in[12];
    const float* bg2   = (const float*)d_in[13];
    const float* Wl    = (const float*)d_in[14];
    const float* bl    = (const float*)d_in[15];
    const float* We_ih = (const float*)d_in[16];
    const float* We_hh = (const float*)d_in[17];
    const float* be_ih = (const float*)d_in[18];
    const float* be_hh = (const float*)d_in[19];
    const float* Wenc  = (const float*)d_in[20];
    const float* benc  = (const float*)d_in[21];

    int B = in_sizes[0] / 48;   // x is [B, 12, 4]
    zt_kernel<<<(B + 63) / 64, 256>>>(z, B);
    stae_main<<<(B + ELPB - 1) / ELPB, TB>>>(
        x, W_ih, W_hh, b_ih, b_hh, mW1, mb1, mW2, mb2,
        Wg, bg, Wg2, bg2, Wl, bl, We_ih, We_hh, be_ih, be_hh,
        Wenc, benc, (float*)d_out, B);
}

// round 14
// speedup vs baseline: 1.6009x; 1.6009x over previous
#include <cuda_runtime.h>

#define TB 128       // 4 warps; each warp owns 32 batch elements
#define ELPB 128     // elements per CTA
#define MAXB 131072
#define SS 33        // stage row stride (floats)
#define HS 17        // hbuf row stride (floats)

typedef unsigned int u32;

// scratch: z transposed [48][B]
__device__ float g_zt[(size_t)48 * MAXB];

__device__ __forceinline__ float tanha(float x) {
    float y; asm("tanh.approx.f32 %0,%1;" : "=f"(y) : "f"(x)); return y;
}
// i/f/o gate rows pre-scaled by 0.5: sigmoid(x) = fmaf(tanh(x/2),0.5,0.5)
__device__ __forceinline__ float sigp(float a_half) {
    return fmaf(tanha(a_half), 0.5f, 0.5f);
}
__device__ __forceinline__ u32 tf32c(float x) {
    u32 r; asm("cvt.rna.tf32.f32 %0,%1;" : "=r"(r) : "f"(x)); return r;
}
__device__ __forceinline__ void mma8(float& d0, float& d1, float& d2, float& d3,
                                     u32 a0, u32 a1, u32 a2, u32 a3,
                                     u32 b0, u32 b1) {
    asm volatile(
        "mma.sync.aligned.m16n8k8.row.col.f32.tf32.tf32.f32 "
        "{%0,%1,%2,%3},{%4,%5,%6,%7},{%8,%9},{%0,%1,%2,%3};"
        : "+f"(d0), "+f"(d1), "+f"(d2), "+f"(d3)
        : "r"(a0), "r"(a1), "r"(a2), "r"(a3), "r"(b0), "r"(b1));
}

// Transpose z [B][48] -> g_zt [48][B].
__global__ void zt_kernel(const float* __restrict__ z, int B)
{
    __shared__ float ts[64 * 49];
    const int e0 = blockIdx.x * 64;
    const int cnt = min(64, B - e0);
    const float4* zp = (const float4*)(z + (size_t)e0 * 48);
    for (int i = threadIdx.x; i < 768; i += 256) {
        int base = i * 4;
        int el = base / 48, v = base % 48;
        if (el < cnt) {
            float4 w = zp[i];
            ts[el * 49 + v] = w.x; ts[el * 49 + v + 1] = w.y;
            ts[el * 49 + v + 2] = w.z; ts[el * 49 + v + 3] = w.w;
        }
    }
    __syncthreads();
    for (int i = threadIdx.x; i < 3072; i += 256) {
        int v = i >> 6, el = i & 63;
        if (el < cnt)
            g_zt[(size_t)v * B + e0 + el] = ts[el * 49 + v];
    }
}

struct __align__(16) EPI {
    float W1[128], Wlf[12 * 16], Wenc[64], W2[32];
    float Blf[12], B1[8], B2m[4], Benc[4], gg[8];
};

__global__ void __launch_bounds__(TB, 2) stae_main(
    const float* __restrict__ x,
    const float* __restrict__ W_ih, const float* __restrict__ W_hh,
    const float* __restrict__ b_ih, const float* __restrict__ b_hh,
    const float* __restrict__ mW1, const float* __restrict__ mb1,
    const float* __restrict__ mW2, const float* __restrict__ mb2,
    const float* __restrict__ Wg, const float* __restrict__ bg,
    const float* __restrict__ Wg2, const float* __restrict__ bg2,
    const float* __restrict__ Wl, const float* __restrict__ bl,
    const float* __restrict__ We_ih, const float* __restrict__ We_hh,
    const float* __restrict__ be_ih, const float* __restrict__ be_hh,
    const float* __restrict__ Wenc, const float* __restrict__ benc,
    float* __restrict__ out, int B)
{
    __shared__ float wc[64 * 24];        // combined gate weights [gate][24] (padded)
    __shared__ float wbias[64];          // scaled bias per gate row
    __shared__ float stage[4 * 48 * SS]; // per-warp input stage (z / en); lut at end
    __shared__ float hbuf[4 * 32 * HS];  // per-warp h (tf32 bits as float)
    __shared__ EPI ep;

    const int tid = threadIdx.x;
    const int lane = tid & 31;
    const int warp = tid >> 5;
    const int g = lane >> 2;     // 0..7
    const int q = lane & 3;      // 0..3

    // ---- prologue: main-LSTM weights + epilogue consts ----------------------
    for (int i = tid; i < 64 * 24; i += TB) {
        int gate = i / 24, k = i % 24;
        float sc = ((gate >> 4) == 2) ? 1.f : 0.5f;
        float v = 0.f;
        if (k < 4) v = W_ih[gate * 4 + k] * sc;
        else if (k < 20) v = W_hh[gate * 16 + (k - 4)] * sc;
        wc[i] = v;
    }
    for (int i = tid; i < 64; i += TB) {
        float sc = ((i >> 4) == 2) ? 1.f : 0.5f;
        wbias[i] = (b_ih[i] + b_hh[i]) * sc;
    }
    for (int i = tid; i < 128; i += TB) ep.W1[i] = mW1[i];
    for (int i = tid; i < 156; i += TB) ep.Wlf[(i / 13) * 16 + (i % 13)] = Wl[i];
    for (int i = tid; i < 64; i += TB) ep.Wenc[i] = Wenc[i];
    if (tid < 32) ep.W2[tid] = mW2[tid];
    if (tid < 12) ep.Blf[tid] = bl[tid];
    if (tid < 8)  ep.B1[tid] = mb1[tid];
    if (tid < 4)  { ep.B2m[tid] = mb2[tid]; ep.Benc[tid] = benc[tid]; }
    if (tid < 3)  { ep.gg[tid] = Wg[tid]; ep.gg[4 + tid] = Wg2[tid]; }
    if (tid == 3) { ep.gg[3] = bg[0]; ep.gg[7] = bg2[0]; }

    const int ctaBase = blockIdx.x * ELPB;
    const int eWarp = ctaBase + warp * 32;       // warp's first element
    float* stg = stage + warp * 48 * SS;
    float* hb = hbuf + warp * 32 * HS;

    // stage this warp's z tile [48][32]
    for (int i = lane; i < 48 * 32; i += 32) {
        int v = i >> 5, r = i & 31;
        int e = eWarp + r; if (e >= B) e = B - 1;
        stg[v * SS + r] = g_zt[(size_t)v * B + e];
    }
    __syncthreads();   // wc/wbias/ep visible

    // ---- load B fragments + bias regs for MAIN LSTM -------------------------
    u32 bfr[8][3][2];
    float bs[8][2];
#pragma unroll
    for (int j = 0; j < 8; j++) {
#pragma unroll
        for (int kt = 0; kt < 3; kt++) {
            bfr[j][kt][0] = tf32c(wc[(8 * j + g) * 24 + 8 * kt + q]);
            bfr[j][kt][1] = tf32c(wc[(8 * j + g) * 24 + 8 * kt + q + 4]);
        }
        bs[j][0] = wbias[8 * j + 2 * q];
        bs[j][1] = wbias[8 * j + 2 * q + 1];
    }

    float c[16];   // c-state: [m][ub][idx] flattened as m*8 + ub*4 + idx
#pragma unroll
    for (int k = 0; k < 16; k++) c[k] = 0.f;
    // zero-init h (each lane owns exactly its 16 (r,u) slots)
#pragma unroll
    for (int m = 0; m < 2; m++)
#pragma unroll
        for (int sidx = 0; sidx < 2; sidx++)
#pragma unroll
            for (int ub = 0; ub < 2; ub++)
#pragma unroll
                for (int p = 0; p < 2; p++)
                    hb[(16 * m + g + 8 * sidx) * HS + 2 * q + p + 8 * ub] = 0.f;

    // ================= recurrent macro-body (used for both phases) ===========
#define LSTM_STEPS()                                                          \
    _Pragma("unroll 1")                                                       \
    for (int t = 0; t < 12; t++) {                                            \
        u32 a[2][3][4];                                                       \
        _Pragma("unroll")                                                     \
        for (int m = 0; m < 2; m++) {                                         \
            int r0 = 16 * m + g, r1 = r0 + 8;                                 \
            a[m][0][0] = tf32c(stg[(4 * t + q) * SS + r0]);                   \
            a[m][0][1] = tf32c(stg[(4 * t + q) * SS + r1]);                   \
            a[m][0][2] = __float_as_uint(hb[r0 * HS + q]);                    \
            a[m][0][3] = __float_as_uint(hb[r1 * HS + q]);                    \
            a[m][1][0] = __float_as_uint(hb[r0 * HS + 4 + q]);                \
            a[m][1][1] = __float_as_uint(hb[r1 * HS + 4 + q]);                \
            a[m][1][2] = __float_as_uint(hb[r0 * HS + 8 + q]);                \
            a[m][1][3] = __float_as_uint(hb[r1 * HS + 8 + q]);                \
            a[m][2][0] = __float_as_uint(hb[r0 * HS + 12 + q]);               \
            a[m][2][1] = __float_as_uint(hb[r1 * HS + 12 + q]);               \
            a[m][2][2] = 0u;                                                  \
            a[m][2][3] = 0u;                                                  \
        }                                                                     \
        float acc[2][8][4];                                                   \
        _Pragma("unroll")                                                     \
        for (int m = 0; m < 2; m++)                                           \
            _Pragma("unroll")                                                 \
            for (int j = 0; j < 8; j++) {                                     \
                acc[m][j][0] = bs[j][0]; acc[m][j][1] = bs[j][1];             \
                acc[m][j][2] = bs[j][0]; acc[m][j][3] = bs[j][1];             \
                _Pragma("unroll")                                             \
                for (int kt = 0; kt < 3; kt++)                                \
                    mma8(acc[m][j][0], acc[m][j][1], acc[m][j][2], acc[m][j][3], \
                         a[m][kt][0], a[m][kt][1], a[m][kt][2], a[m][kt][3],  \
                         bfr[j][kt][0], bfr[j][kt][1]);                       \
            }                                                                 \
        _Pragma("unroll")                                                     \
        for (int m = 0; m < 2; m++)                                           \
            _Pragma("unroll")                                                 \
            for (int ub = 0; ub < 2; ub++)                                    \
                _Pragma("unroll")                                             \
                for (int idx = 0; idx < 4; idx++) {                           \
                    float iv = acc[m][0 + ub][idx];                           \
                    float fv = acc[m][2 + ub][idx];                           \
                    float gv = acc[m][4 + ub][idx];                           \
                    float ov = acc[m][6 + ub][idx];                           \
                    int ci = m * 8 + ub * 4 + idx;                            \
                    float cn = sigp(fv) * c[ci] + sigp(iv) * tanha(gv);       \
                    c[ci] = cn;                                               \
                    float hv = sigp(ov) * tanha(cn);                          \
                    int r = 16 * m + g + 8 * (idx >> 1);                      \
                    int u = 2 * q + (idx & 1) + 8 * ub;                       \
                    hb[r * HS + u] = __uint_as_float(tf32c(hv));              \
                }                                                             \
    }

    // ---------------- phase 1: main LSTM over z ------------------------------
    LSTM_STEPS();

    // ------------- epilogue: 1 elem/thread: mlp -> gcn2 -> v_out -> en -------
    {
        const int eg = eWarp + lane;                  // this thread's element
        const int e = (eg < B) ? eg : B - 1;
        float hs[16];
#pragma unroll
        for (int k = 0; k < 16; k++) hs[k] = hb[lane * HS + k];
        float m1[8];
#pragma unroll
        for (int jj = 0; jj < 8; jj++) {
            float a = ep.B1[jj];
#pragma unroll
            for (int k = 0; k < 16; k++) a += hs[k] * ep.W1[jj * 16 + k];
            m1[jj] = fmaxf(a, 0.f);
        }
        float mo[4];
#pragma unroll
        for (int n = 0; n < 4; n++) {
            float a = ep.B2m[n];
#pragma unroll
            for (int jj = 0; jj < 8; jj++) a += m1[jj] * ep.W2[n * 8 + jj];
            mo[n] = a;
        }
        float q0 = ep.gg[4], q1 = ep.gg[5], q2 = ep.gg[6], qb = ep.gg[7];
        float x1_0 = mo[1], x1_1 = mo[0] + mo[2], x1_2 = mo[1] + mo[3], x1_3 = mo[2];
        float x2_0 = x1_1, x2_1 = x1_0 + x1_2, x2_2 = x1_1 + x1_3, x2_3 = x1_2;
        float mg[4];
        mg[0] = q0 * mo[0] + q1 * x1_0 + q2 * x2_0 + qb;
        mg[1] = q0 * mo[1] + q1 * x1_1 + q2 * x2_1 + qb;
        mg[2] = q0 * mo[2] + q1 * x1_2 + q2 * x2_2 + qb;
        mg[3] = q0 * mo[3] + q1 * x1_3 + q2 * x2_3 + qb;

        float xr[48];
        {
            const float4* xb = (const float4*)(x + (size_t)e * 48);
#pragma unroll
            for (int qq = 0; qq < 12; qq++) {
                float4 v = xb[qq];
                xr[qq * 4 + 0] = v.x; xr[qq * 4 + 1] = v.y;
                xr[qq * 4 + 2] = v.z; xr[qq * 4 + 3] = v.w;
            }
        }
        const float g0_ = ep.gg[0], g1_ = ep.gg[1], g2_ = ep.gg[2], gb_ = ep.gg[3];
#pragma unroll 1
        for (int t = 0; t < 12; t++) {
            float vc[4];
#pragma unroll
            for (int n = 0; n < 4; n++) {
                float a = ep.Blf[t] + mg[n] * ep.Wlf[t * 16 + 12];
#pragma unroll
                for (int k = 0; k < 12; k++) a += xr[n * 12 + k] * ep.Wlf[t * 16 + k];
                vc[n] = a;
            }
            float xc0 = xr[t], xc1 = xr[12 + t], xc2 = xr[24 + t], xc3 = xr[36 + t];
            float a1_0 = xc1, a1_1 = xc0 + xc2, a1_2 = xc1 + xc3, a1_3 = xc2;
            float a2_0 = a1_1, a2_1 = a1_0 + a1_2, a2_2 = a1_1 + a1_3, a2_3 = a1_2;
            float d1_0 = vc[1], d1_1 = vc[0] + vc[2], d1_2 = vc[1] + vc[3], d1_3 = vc[2];
            float d2_0 = d1_1, d2_1 = d1_0 + d1_2, d2_2 = d1_1 + d1_3, d2_3 = d1_2;
            stg[(4 * t + 0) * SS + lane] = g0_ * xc0 + g1_ * a1_0 + g2_ * a2_0 + gb_
                                         + q0 * vc[0] + q1 * d1_0 + q2 * d2_0 + qb;
            stg[(4 * t + 1) * SS + lane] = g0_ * xc1 + g1_ * a1_1 + g2_ * a2_1 + gb_
                                         + q0 * vc[1] + q1 * d1_1 + q2 * d2_1 + qb;
            stg[(4 * t + 2) * SS + lane] = g0_ * xc2 + g1_ * a1_2 + g2_ * a2_2 + gb_
                                         + q0 * vc[2] + q1 * d1_2 + q2 * d2_2 + qb;
            stg[(4 * t + 3) * SS + lane] = g0_ * xc3 + g1_ * a1_3 + g2_ * a2_3 + gb_
                                         + q0 * vc[3] + q1 * d1_3 + q2 * d2_3 + qb;
        }
    }

    // ---------------- phase switch: encoder weights --------------------------
    __syncthreads();
    for (int i = tid; i < 64 * 24; i += TB) {
        int gate = i / 24, k = i % 24;
        float sc = ((gate >> 4) == 2) ? 1.f : 0.5f;
        float v = 0.f;
        if (k < 4) v = We_ih[gate * 4 + k] * sc;
        else if (k < 20) v = We_hh[gate * 16 + (k - 4)] * sc;
        wc[i] = v;
    }
    for (int i = tid; i < 64; i += TB) {
        float sc = ((i >> 4) == 2) ? 1.f : 0.5f;
        wbias[i] = (be_ih[i] + be_hh[i]) * sc;
    }
    __syncthreads();
#pragma unroll
    for (int j = 0; j < 8; j++) {
#pragma unroll
        for (int kt = 0; kt < 3; kt++) {
            bfr[j][kt][0] = tf32c(wc[(8 * j + g) * 24 + 8 * kt + q]);
            bfr[j][kt][1] = tf32c(wc[(8 * j + g) * 24 + 8 * kt + q + 4]);
        }
        bs[j][0] = wbias[8 * j + 2 * q];
        bs[j][1] = wbias[8 * j + 2 * q + 1];
    }
#pragma unroll
    for (int k = 0; k < 16; k++) c[k] = 0.f;
#pragma unroll
    for (int m = 0; m < 2; m++)
#pragma unroll
        for (int sidx = 0; sidx < 2; sidx++)
#pragma unroll
            for (int ub = 0; ub < 2; ub++)
#pragma unroll
                for (int p = 0; p < 2; p++)
                    hb[(16 * m + g + 8 * sidx) * HS + 2 * q + p + 8 * ub] = 0.f;

    // ---------------- phase 3: encoder LSTM over en (in stg) -----------------
    LSTM_STEPS();

    // ---------------- final projection -> lut -> coalesced write -------------
    __syncthreads();   // all warps done reading stage before lut overlay
    float* lutF = stage;   // flat: [128 elems][4]
    {
        float hs[16];
#pragma unroll
        for (int k = 0; k < 16; k++) hs[k] = hb[lane * HS + k];
#pragma unroll
        for (int n = 0; n < 4; n++) {
            float a = ep.Benc[n];
#pragma unroll
            for (int k = 0; k < 16; k++) a += hs[k] * ep.Wenc[n * 16 + k];
            lutF[(warp * 32 + lane) * 4 + n] = a;
        }
    }
    __syncthreads();

    float4* ob = (float4*)(out + (size_t)ctaBase * 48);
#pragma unroll 1
    for (int r = 0; r < 12; r++) {
        int f = r * TB + tid;
        int el = f / 12;
        int jj = f % 12;
        if (ctaBase + el < B) {
            float v = lutF[el * 4 + jj / 3];
            ob[f] = make_float4(v, v, v, v);
        }
    }
}

extern "C" void kernel_launch(void* const* d_in, const int* in_sizes, int n_in,
                              void* d_out, int out_size)
{
    const float* x     = (const float*)d_in[0];
    const float* z     = (const float*)d_in[1];
    const float* W_ih  = (const float*)d_in[2];
    const float* W_hh  = (const float*)d_in[3];
    const float* b_ih  = (const float*)d_in[4];
    const float* b_hh  = (const float*)d_in[5];
    const float* mW1   = (const float*)d_in[6];
    const float* mb1   = (const float*)d_in[7];
    const float* mW2   = (const float*)d_in[8];
    const float* mb2   = (const float*)d_in[9];
    const float* Wg    = (const float*)d_in[10];
    const float* bg    = (const float*)d_in[11];
    const float* Wg2   = (const float*)d_in[12];
    const float* bg2   = (const float*)d_in[13];
    const float* Wl    = (const float*)d_in[14];
    const float* bl    = (const float*)d_in[15];
    const float* We_ih = (const float*)d_in[16];
    const float* We_hh = (const float*)d_in[17];
    const float* be_ih = (const float*)d_in[18];
    const float* be_hh = (const float*)d_in[19];
    const float* Wenc  = (const float*)d_in[20];
    const float* benc  = (const float*)d_in[21];

    int B = in_sizes[0] / 48;   // x is [B, 12, 4]
    zt_kernel<<<(B + 63) / 64, 256>>>(z, B);
    stae_main<<<(B + ELPB - 1) / ELPB, TB>>>(
        x, W_ih, W_hh, b_ih, b_hh, mW1, mb1, mW2, mb2,
        Wg, bg, Wg2, bg2, Wl, bl, We_ih, We_hh, be_ih, be_hh,
        Wenc, benc, (float*)d_out, B);
}

// round 15
// speedup vs baseline: 1.8675x; 1.1665x over previous
#include <cuda_runtime.h>

#define TB 128       // 4 warps; each warp owns 32 batch elements
#define ELPB 128     // elements per CTA
#define MAXB 131072
#define SS 33        // stage row stride (floats)
#define HS 17        // hbuf row stride (floats)

typedef unsigned int u32;

// scratch: z transposed [48][B]
__device__ float g_zt[(size_t)48 * MAXB];

__device__ __forceinline__ float tanha(float x) {
    float y; asm("tanh.approx.f32 %0,%1;" : "=f"(y) : "f"(x)); return y;
}
// i/f/o gate rows pre-scaled by 0.5: sigmoid(x) = fmaf(tanh(x/2),0.5,0.5)
__device__ __forceinline__ float sigp(float a_half) {
    return fmaf(tanha(a_half), 0.5f, 0.5f);
}
__device__ __forceinline__ u32 tf32c(float x) {
    u32 r; asm("cvt.rna.tf32.f32 %0,%1;" : "=r"(r) : "f"(x)); return r;
}
__device__ __forceinline__ void mma8(float& d0, float& d1, float& d2, float& d3,
                                     u32 a0, u32 a1, u32 a2, u32 a3,
                                     u32 b0, u32 b1) {
    asm volatile(
        "mma.sync.aligned.m16n8k8.row.col.f32.tf32.tf32.f32 "
        "{%0,%1,%2,%3},{%4,%5,%6,%7},{%8,%9},{%0,%1,%2,%3};"
        : "+f"(d0), "+f"(d1), "+f"(d2), "+f"(d3)
        : "r"(a0), "r"(a1), "r"(a2), "r"(a3), "r"(b0), "r"(b1));
}

// Transpose z [B][48] -> g_zt [48][B].
__global__ void zt_kernel(const float* __restrict__ z, int B)
{
    __shared__ float ts[64 * 49];
    const int e0 = blockIdx.x * 64;
    const int cnt = min(64, B - e0);
    const float4* zp = (const float4*)(z + (size_t)e0 * 48);
    for (int i = threadIdx.x; i < 768; i += 256) {
        int base = i * 4;
        int el = base / 48, v = base % 48;
        if (el < cnt) {
            float4 w = zp[i];
            ts[el * 49 + v] = w.x; ts[el * 49 + v + 1] = w.y;
            ts[el * 49 + v + 2] = w.z; ts[el * 49 + v + 3] = w.w;
        }
    }
    __syncthreads();
    for (int i = threadIdx.x; i < 3072; i += 256) {
        int v = i >> 6, el = i & 63;
        if (el < cnt)
            g_zt[(size_t)v * B + e0 + el] = ts[el * 49 + v];
    }
}

struct __align__(16) EPI {
    float W1[128], Wlf[12 * 16], Wenc[64], W2[32];
    float Blf[12], B1[8], B2m[4], Benc[4], gg[8];
};

__global__ void __launch_bounds__(TB, 3) stae_main(
    const float* __restrict__ x,
    const float* __restrict__ W_ih, const float* __restrict__ W_hh,
    const float* __restrict__ b_ih, const float* __restrict__ b_hh,
    const float* __restrict__ mW1, const float* __restrict__ mb1,
    const float* __restrict__ mW2, const float* __restrict__ mb2,
    const float* __restrict__ Wg, const float* __restrict__ bg,
    const float* __restrict__ Wg2, const float* __restrict__ bg2,
    const float* __restrict__ Wl, const float* __restrict__ bl,
    const float* __restrict__ We_ih, const float* __restrict__ We_hh,
    const float* __restrict__ be_ih, const float* __restrict__ be_hh,
    const float* __restrict__ Wenc, const float* __restrict__ benc,
    float* __restrict__ out, int B)
{
    __shared__ float wc[64 * 24];        // combined gate weights [gate][24] (padded)
    __shared__ float wbias[64];          // scaled bias per gate row
    __shared__ float stage[4 * 48 * SS]; // per-warp input stage (z / en); lut at end
    __shared__ float hbuf[4 * 32 * HS];  // per-warp h (tf32 bits as float)
    __shared__ EPI ep;

    const int tid = threadIdx.x;
    const int lane = tid & 31;
    const int warp = tid >> 5;
    const int g = lane >> 2;     // 0..7
    const int q = lane & 3;      // 0..3

    // ---- prologue: main-LSTM weights + epilogue consts ----------------------
    for (int i = tid; i < 64 * 24; i += TB) {
        int gate = i / 24, k = i % 24;
        float sc = ((gate >> 4) == 2) ? 1.f : 0.5f;
        float v = 0.f;
        if (k < 4) v = W_ih[gate * 4 + k] * sc;
        else if (k < 20) v = W_hh[gate * 16 + (k - 4)] * sc;
        wc[i] = v;
    }
    for (int i = tid; i < 64; i += TB) {
        float sc = ((i >> 4) == 2) ? 1.f : 0.5f;
        wbias[i] = (b_ih[i] + b_hh[i]) * sc;
    }
    for (int i = tid; i < 128; i += TB) ep.W1[i] = mW1[i];
    for (int i = tid; i < 156; i += TB) ep.Wlf[(i / 13) * 16 + (i % 13)] = Wl[i];
    for (int i = tid; i < 64; i += TB) ep.Wenc[i] = Wenc[i];
    if (tid < 32) ep.W2[tid] = mW2[tid];
    if (tid < 12) ep.Blf[tid] = bl[tid];
    if (tid < 8)  ep.B1[tid] = mb1[tid];
    if (tid < 4)  { ep.B2m[tid] = mb2[tid]; ep.Benc[tid] = benc[tid]; }
    if (tid < 3)  { ep.gg[tid] = Wg[tid]; ep.gg[4 + tid] = Wg2[tid]; }
    if (tid == 3) { ep.gg[3] = bg[0]; ep.gg[7] = bg2[0]; }

    const int ctaBase = blockIdx.x * ELPB;
    const int eWarp = ctaBase + warp * 32;       // warp's first element
    float* stg = stage + warp * 48 * SS;
    float* hb = hbuf + warp * 32 * HS;

    // stage this warp's z tile [48][32]
    for (int i = lane; i < 48 * 32; i += 32) {
        int v = i >> 5, r = i & 31;
        int e = eWarp + r; if (e >= B) e = B - 1;
        stg[v * SS + r] = g_zt[(size_t)v * B + e];
    }
    __syncthreads();   // wc/wbias/ep visible

    // ---- load B fragments + bias regs for MAIN LSTM -------------------------
    u32 bfr[8][3][2];
    float bs[8][2];
#pragma unroll
    for (int j = 0; j < 8; j++) {
#pragma unroll
        for (int kt = 0; kt < 3; kt++) {
            bfr[j][kt][0] = tf32c(wc[(8 * j + g) * 24 + 8 * kt + q]);
            bfr[j][kt][1] = tf32c(wc[(8 * j + g) * 24 + 8 * kt + q + 4]);
        }
        bs[j][0] = wbias[8 * j + 2 * q];
        bs[j][1] = wbias[8 * j + 2 * q + 1];
    }

    float c[16];   // c-state: [m][ub][idx] flattened as m*8 + ub*4 + idx
#pragma unroll
    for (int k = 0; k < 16; k++) c[k] = 0.f;
    // zero-init h (each lane owns exactly its 16 (r,u) slots)
#pragma unroll
    for (int m = 0; m < 2; m++)
#pragma unroll
        for (int sidx = 0; sidx < 2; sidx++)
#pragma unroll
            for (int ub = 0; ub < 2; ub++)
#pragma unroll
                for (int p = 0; p < 2; p++)
                    hb[(16 * m + g + 8 * sidx) * HS + 2 * q + p + 8 * ub] = 0.f;

    // ========== recurrent macro-body: (m, ub)-grouped for low reg peak =======
#define LSTM_STEPS()                                                          \
    _Pragma("unroll 1")                                                       \
    for (int t = 0; t < 12; t++) {                                            \
        _Pragma("unroll")                                                     \
        for (int m = 0; m < 2; m++) {                                         \
            int r0 = 16 * m + g, r1 = r0 + 8;                                 \
            u32 a[3][4];                                                      \
            a[0][0] = tf32c(stg[(4 * t + q) * SS + r0]);                      \
            a[0][1] = tf32c(stg[(4 * t + q) * SS + r1]);                      \
            a[0][2] = __float_as_uint(hb[r0 * HS + q]);                       \
            a[0][3] = __float_as_uint(hb[r1 * HS + q]);                       \
            a[1][0] = __float_as_uint(hb[r0 * HS + 4 + q]);                   \
            a[1][1] = __float_as_uint(hb[r1 * HS + 4 + q]);                   \
            a[1][2] = __float_as_uint(hb[r0 * HS + 8 + q]);                   \
            a[1][3] = __float_as_uint(hb[r1 * HS + 8 + q]);                   \
            a[2][0] = __float_as_uint(hb[r0 * HS + 12 + q]);                  \
            a[2][1] = __float_as_uint(hb[r1 * HS + 12 + q]);                  \
            a[2][2] = 0u;                                                     \
            a[2][3] = 0u;                                                     \
            _Pragma("unroll")                                                 \
            for (int ub = 0; ub < 2; ub++) {                                  \
                float ac[4][4];                                               \
                _Pragma("unroll")                                             \
                for (int jj = 0; jj < 4; jj++) {                              \
                    int j = 2 * jj + ub;                                      \
                    ac[jj][0] = bs[j][0]; ac[jj][1] = bs[j][1];               \
                    ac[jj][2] = bs[j][0]; ac[jj][3] = bs[j][1];               \
                    _Pragma("unroll")                                         \
                    for (int kt = 0; kt < 3; kt++)                            \
                        mma8(ac[jj][0], ac[jj][1], ac[jj][2], ac[jj][3],      \
                             a[kt][0], a[kt][1], a[kt][2], a[kt][3],          \
                             bfr[j][kt][0], bfr[j][kt][1]);                   \
                }                                                             \
                _Pragma("unroll")                                             \
                for (int idx = 0; idx < 4; idx++) {                           \
                    float iv = ac[0][idx];                                    \
                    float fv = ac[1][idx];                                    \
                    float gv = ac[2][idx];                                    \
                    float ov = ac[3][idx];                                    \
                    int ci = m * 8 + ub * 4 + idx;                            \
                    float cn = sigp(fv) * c[ci] + sigp(iv) * tanha(gv);       \
                    c[ci] = cn;                                               \
                    float hv = sigp(ov) * tanha(cn);                          \
                    int r = 16 * m + g + 8 * (idx >> 1);                      \
                    int u = 2 * q + (idx & 1) + 8 * ub;                       \
                    hb[r * HS + u] = __uint_as_float(tf32c(hv));              \
                }                                                             \
            }                                                                 \
        }                                                                     \
    }

    // ---------------- phase 1: main LSTM over z ------------------------------
    LSTM_STEPS();

    // ------------- epilogue: 1 elem/thread: mlp -> gcn2 -> v_out -> en -------
    {
        const int eg = eWarp + lane;                  // this thread's element
        const int e = (eg < B) ? eg : B - 1;
        float hs[16];
#pragma unroll
        for (int k = 0; k < 16; k++) hs[k] = hb[lane * HS + k];
        float m1[8];
#pragma unroll
        for (int jj = 0; jj < 8; jj++) {
            float a = ep.B1[jj];
#pragma unroll
            for (int k = 0; k < 16; k++) a += hs[k] * ep.W1[jj * 16 + k];
            m1[jj] = fmaxf(a, 0.f);
        }
        float mo[4];
#pragma unroll
        for (int n = 0; n < 4; n++) {
            float a = ep.B2m[n];
#pragma unroll
            for (int jj = 0; jj < 8; jj++) a += m1[jj] * ep.W2[n * 8 + jj];
            mo[n] = a;
        }
        float q0 = ep.gg[4], q1 = ep.gg[5], q2 = ep.gg[6], qb = ep.gg[7];
        float x1_0 = mo[1], x1_1 = mo[0] + mo[2], x1_2 = mo[1] + mo[3], x1_3 = mo[2];
        float x2_0 = x1_1, x2_1 = x1_0 + x1_2, x2_2 = x1_1 + x1_3, x2_3 = x1_2;
        float mg[4];
        mg[0] = q0 * mo[0] + q1 * x1_0 + q2 * x2_0 + qb;
        mg[1] = q0 * mo[1] + q1 * x1_1 + q2 * x2_1 + qb;
        mg[2] = q0 * mo[2] + q1 * x1_2 + q2 * x2_2 + qb;
        mg[3] = q0 * mo[3] + q1 * x1_3 + q2 * x2_3 + qb;

        float xr[48];
        {
            const float4* xb = (const float4*)(x + (size_t)e * 48);
#pragma unroll
            for (int qq = 0; qq < 12; qq++) {
                float4 v = xb[qq];
                xr[qq * 4 + 0] = v.x; xr[qq * 4 + 1] = v.y;
                xr[qq * 4 + 2] = v.z; xr[qq * 4 + 3] = v.w;
            }
        }
        const float g0_ = ep.gg[0], g1_ = ep.gg[1], g2_ = ep.gg[2], gb_ = ep.gg[3];
#pragma unroll 1
        for (int t = 0; t < 12; t++) {
            float vc[4];
#pragma unroll
            for (int n = 0; n < 4; n++) {
                float a = ep.Blf[t] + mg[n] * ep.Wlf[t * 16 + 12];
#pragma unroll
                for (int k = 0; k < 12; k++) a += xr[n * 12 + k] * ep.Wlf[t * 16 + k];
                vc[n] = a;
            }
            float xc0 = xr[t], xc1 = xr[12 + t], xc2 = xr[24 + t], xc3 = xr[36 + t];
            float a1_0 = xc1, a1_1 = xc0 + xc2, a1_2 = xc1 + xc3, a1_3 = xc2;
            float a2_0 = a1_1, a2_1 = a1_0 + a1_2, a2_2 = a1_1 + a1_3, a2_3 = a1_2;
            float d1_0 = vc[1], d1_1 = vc[0] + vc[2], d1_2 = vc[1] + vc[3], d1_3 = vc[2];
            float d2_0 = d1_1, d2_1 = d1_0 + d1_2, d2_2 = d1_1 + d1_3, d2_3 = d1_2;
            stg[(4 * t + 0) * SS + lane] = g0_ * xc0 + g1_ * a1_0 + g2_ * a2_0 + gb_
                                         + q0 * vc[0] + q1 * d1_0 + q2 * d2_0 + qb;
            stg[(4 * t + 1) * SS + lane] = g0_ * xc1 + g1_ * a1_1 + g2_ * a2_1 + gb_
                                         + q0 * vc[1] + q1 * d1_1 + q2 * d2_1 + qb;
            stg[(4 * t + 2) * SS + lane] = g0_ * xc2 + g1_ * a1_2 + g2_ * a2_2 + gb_
                                         + q0 * vc[2] + q1 * d1_2 + q2 * d2_2 + qb;
            stg[(4 * t + 3) * SS + lane] = g0_ * xc3 + g1_ * a1_3 + g2_ * a2_3 + gb_
                                         + q0 * vc[3] + q1 * d1_3 + q2 * d2_3 + qb;
        }
    }

    // ---------------- phase switch: encoder weights --------------------------
    __syncthreads();
    for (int i = tid; i < 64 * 24; i += TB) {
        int gate = i / 24, k = i % 24;
        float sc = ((gate >> 4) == 2) ? 1.f : 0.5f;
        float v = 0.f;
        if (k < 4) v = We_ih[gate * 4 + k] * sc;
        else if (k < 20) v = We_hh[gate * 16 + (k - 4)] * sc;
        wc[i] = v;
    }
    for (int i = tid; i < 64; i += TB) {
        float sc = ((i >> 4) == 2) ? 1.f : 0.5f;
        wbias[i] = (be_ih[i] + be_hh[i]) * sc;
    }
    __syncthreads();
#pragma unroll
    for (int j = 0; j < 8; j++) {
#pragma unroll
        for (int kt = 0; kt < 3; kt++) {
            bfr[j][kt][0] = tf32c(wc[(8 * j + g) * 24 + 8 * kt + q]);
            bfr[j][kt][1] = tf32c(wc[(8 * j + g) * 24 + 8 * kt + q + 4]);
        }
        bs[j][0] = wbias[8 * j + 2 * q];
        bs[j][1] = wbias[8 * j + 2 * q + 1];
    }
#pragma unroll
    for (int k = 0; k < 16; k++) c[k] = 0.f;
#pragma unroll
    for (int m = 0; m < 2; m++)
#pragma unroll
        for (int sidx = 0; sidx < 2; sidx++)
#pragma unroll
            for (int ub = 0; ub < 2; ub++)
#pragma unroll
                for (int p = 0; p < 2; p++)
                    hb[(16 * m + g + 8 * sidx) * HS + 2 * q + p + 8 * ub] = 0.f;

    // ---------------- phase 3: encoder LSTM over en (in stg) -----------------
    LSTM_STEPS();

    // ---------------- final projection -> lut -> coalesced write -------------
    __syncthreads();   // all warps done reading stage before lut overlay
    float* lutF = stage;   // flat: [128 elems][4]
    {
        float hs[16];
#pragma unroll
        for (int k = 0; k < 16; k++) hs[k] = hb[lane * HS + k];
#pragma unroll
        for (int n = 0; n < 4; n++) {
            float a = ep.Benc[n];
#pragma unroll
            for (int k = 0; k < 16; k++) a += hs[k] * ep.Wenc[n * 16 + k];
            lutF[(warp * 32 + lane) * 4 + n] = a;
        }
    }
    __syncthreads();

    float4* ob = (float4*)(out + (size_t)ctaBase * 48);
#pragma unroll 1
    for (int r = 0; r < 12; r++) {
        int f = r * TB + tid;
        int el = f / 12;
        int jj = f % 12;
        if (ctaBase + el < B) {
            float v = lutF[el * 4 + jj / 3];
            ob[f] = make_float4(v, v, v, v);
        }
    }
}

extern "C" void kernel_launch(void* const* d_in, const int* in_sizes, int n_in,
                              void* d_out, int out_size)
{
    const float* x     = (const float*)d_in[0];
    const float* z     = (const float*)d_in[1];
    const float* W_ih  = (const float*)d_in[2];
    const float* W_hh  = (const float*)d_in[3];
    const float* b_ih  = (const float*)d_in[4];
    const float* b_hh  = (const float*)d_in[5];
    const float* mW1   = (const float*)d_in[6];
    const float* mb1   = (const float*)d_in[7];
    const float* mW2   = (const float*)d_in[8];
    const float* mb2   = (const float*)d_in[9];
    const float* Wg    = (const float*)d_in[10];
    const float* bg    = (const float*)d_in[11];
    const float* Wg2   = (const float*)d_in[12];
    const float* bg2   = (const float*)d_in[13];
    const float* Wl    = (const float*)d_in[14];
    const float* bl    = (const float*)d_in[15];
    const float* We_ih = (const float*)d_in[16];
    const float* We_hh = (const float*)d_in[17];
    const float* be_ih = (const float*)d_in[18];
    const float* be_hh = (const float*)d_in[19];
    const float* Wenc  = (const float*)d_in[20];
    const float* benc  = (const float*)d_in[21];

    int B = in_sizes[0] / 48;   // x is [B, 12, 4]
    zt_kernel<<<(B + 63) / 64, 256>>>(z, B);
    stae_main<<<(B + ELPB - 1) / ELPB, TB>>>(
        x, W_ih, W_hh, b_ih, b_hh, mW1, mb1, mW2, mb2,
        Wg, bg, Wg2, bg2, Wl, bl, We_ih, We_hh, be_ih, be_hh,
        Wenc, benc, (float*)d_out, B);
}